// round 3
// baseline (speedup 1.0000x reference)
#include <cuda_runtime.h>
#include <cuda_fp16.h>
#include <cstdint>

// ---------------- problem constants ----------------
#define NSAMP   131072
#define INF     8
#define NPCE    495
#define KPAD    512
#define NOUT    256
#define MTILE   128          // CTA rows
#define NTILE   128          // CTA cols
#define KC      32           // K per pipeline chunk
#define NCHUNK  (KPAD / KC)  // 16
#define NTHREADS 256
#define HSTRIDE 41           // 40 H-values + 1 pad (odd -> fewer conflicts)

// smem byte layout (dynamic)
#define OFF_MI  0                       // 512 * 4       = 2048
#define OFF_H   2048                    // 128 * 41 * 4  = 20992 -> 23040
#define OFF_A   23040                   // 2 * 128 * 80  = 20480 -> 43520
#define OFF_B   43520                   // 2 * 128 * 80  = 20480 -> 64000
#define ABUF_BYTES 10240                // 128 rows * 80B (32 halves + 8 pad)
#define BBUF_BYTES 10240
#define ROWB    80                      // padded row stride in bytes
#define SMEM_BYTES 64000

// fp16 weights, zero-padded K, [NOUT][KPAD]
__device__ __half w16g[NOUT * KPAD];

__global__ void convert_w_kernel(const float* __restrict__ wgt) {
    int idx = blockIdx.x * blockDim.x + threadIdx.x;   // 131072 total
    int n = idx >> 9, k = idx & (KPAD - 1);
    w16g[idx] = __float2half(k < NPCE ? wgt[n * NPCE + k] : 0.0f);
}

static __device__ __forceinline__ uint32_t smem_u32(const void* p) {
    uint32_t a;
    asm("{ .reg .u64 t; cvta.to.shared.u64 t, %1; cvt.u32.u64 %0, t; }" : "=r"(a) : "l"(p));
    return a;
}

static __device__ __forceinline__ void cp_async16(uint32_t dst, const void* src) {
    asm volatile("cp.async.ca.shared.global [%0], [%1], 16;" :: "r"(dst), "l"(src));
}

#define CP_COMMIT() asm volatile("cp.async.commit_group;" ::: "memory")
#define CP_WAIT0()  asm volatile("cp.async.wait_group 0;" ::: "memory")

static __device__ __forceinline__ void ldm_x4(uint32_t& r0, uint32_t& r1,
                                              uint32_t& r2, uint32_t& r3, uint32_t addr) {
    asm volatile("ldmatrix.sync.aligned.m8n8.x4.shared.b16 {%0,%1,%2,%3}, [%4];"
                 : "=r"(r0), "=r"(r1), "=r"(r2), "=r"(r3) : "r"(addr));
}

static __device__ __forceinline__ void mma16816(float& c0, float& c1, float& c2, float& c3,
                                                uint32_t a0, uint32_t a1, uint32_t a2, uint32_t a3,
                                                uint32_t b0, uint32_t b1) {
    asm volatile(
        "mma.sync.aligned.m16n8k16.row.col.f32.f16.f16.f32 "
        "{%0,%1,%2,%3}, {%4,%5,%6,%7}, {%8,%9}, {%0,%1,%2,%3};"
        : "+f"(c0), "+f"(c1), "+f"(c2), "+f"(c3)
        : "r"(a0), "r"(a1), "r"(a2), "r"(a3), "r"(b0), "r"(b1));
}

extern __shared__ char smem[];

__global__ void __launch_bounds__(NTHREADS, 2)
pce_mma_kernel(const float* __restrict__ x, const int* __restrict__ mi,
               float* __restrict__ out)
{
    const int tid  = threadIdx.x;
    const int wid  = tid >> 5;
    const int lane = tid & 31;
    const int bm   = blockIdx.x >> 1;       // m tile id (0..1023)
    const int bn   = blockIdx.x & 1;        // n tile id (0..1)
    const int m0   = bm * MTILE;
    const int n0   = bn * NTILE;

    const uint32_t sbase = smem_u32(smem);
    unsigned* mi_s = (unsigned*)(smem + OFF_MI);
    float*    hbuf = (float*)(smem + OFF_H);

    // ---- pack multi-indices: <= 4 nonzero (dim, order) entries.
    //      6-bit slots (offsets reach 7*5+4 = 39; 5 bits overflowed -> R2 bug)
    for (int t = tid; t < KPAD; t += NTHREADS) {
        unsigned packed = 0;
        if (t < NPCE) {
            int slot = 0;
            #pragma unroll
            for (int j = 0; j < INF; j++) {
                int o = mi[t * INF + j];
                if (o > 0) { packed |= (unsigned)(j * 5 + o) << (6 * slot); slot++; }
            }
        }
        mi_s[t] = packed;
    }

    // ---- normalized probabilists' Hermite table for this tile's 128 samples ----
    if (tid < MTILE) {
        const float4* xr = (const float4*)(x + (size_t)(m0 + tid) * INF);
        float4 xa = xr[0], xb = xr[1];
        float vx[8] = {xa.x, xa.y, xa.z, xa.w, xb.x, xb.y, xb.z, xb.w};
        float* hr = hbuf + tid * HSTRIDE;
        #pragma unroll
        for (int j = 0; j < INF; j++) {
            float v  = vx[j];
            float h2 = v * v - 1.f;
            float h3 = v * h2 - 2.f * v;
            float h4 = v * h3 - 3.f * h2;
            hr[j * 5 + 0] = 1.f;
            hr[j * 5 + 1] = v;
            hr[j * 5 + 2] = h2 * 0.70710678118654752f;  // 1/sqrt(2!)
            hr[j * 5 + 3] = h3 * 0.40824829046386302f;  // 1/sqrt(3!)
            hr[j * 5 + 4] = h4 * 0.20412414523193151f;  // 1/sqrt(4!)
        }
    }
    __syncthreads();

    // ---- pipeline helpers ----
    auto load_B = [&](int c, int buf) {
        // B tile: 128 n-rows x 32 k halves = 128 rows x 64B; 512 x 16B chunks
        const uint32_t bdst = sbase + OFF_B + buf * BBUF_BYTES;
        #pragma unroll
        for (int j = 0; j < 2; j++) {
            int idx = tid + j * NTHREADS;        // 0..511
            int n = idx >> 2, g = idx & 3;
            cp_async16(bdst + n * ROWB + g * 16,
                       w16g + (size_t)(n0 + n) * KPAD + c * KC + g * 8);
        }
    };

    auto gen_psi = [&](int c, int buf) {
        // A tile: 128 m-rows x 32 k halves; one half2 per element-pair
        const int k0 = c * KC;
        #pragma unroll
        for (int i = 0; i < 8; i++) {
            int idx = tid + i * NTHREADS;        // 0..2047 = 128 m * 16 half2
            int m = idx >> 4, kp = idx & 15;
            const float* hr = hbuf + m * HSTRIDE;
            unsigned p0 = mi_s[k0 + 2 * kp];
            unsigned p1 = mi_s[k0 + 2 * kp + 1];
            float v0 = hr[p0 & 63] * hr[(p0 >> 6) & 63]
                     * hr[(p0 >> 12) & 63] * hr[(p0 >> 18) & 63];
            float v1 = hr[p1 & 63] * hr[(p1 >> 6) & 63]
                     * hr[(p1 >> 12) & 63] * hr[(p1 >> 18) & 63];
            // k >= NPCE: weight rows are zero-padded, psi value irrelevant
            *(__half2*)(smem + OFF_A + buf * ABUF_BYTES + m * ROWB + kp * 4)
                = __floats2half2_rn(v0, v1);
        }
    };

    // ---- warp tiling: 2(m) x 4(n) warps, each 64m x 32n ----
    const int warp_m = wid >> 2;   // 0..1
    const int warp_n = wid & 3;    // 0..3

    float acc[4][4][4];
    #pragma unroll
    for (int a = 0; a < 4; a++)
        #pragma unroll
        for (int b = 0; b < 4; b++)
            #pragma unroll
            for (int r = 0; r < 4; r++) acc[a][b][r] = 0.f;

    // prologue: fill stage 0
    load_B(0, 0);
    CP_COMMIT();
    gen_psi(0, 0);
    CP_WAIT0();
    __syncthreads();

    for (int c = 0; c < NCHUNK; c++) {
        const int cb = c & 1;
        if (c + 1 < NCHUNK) {
            load_B(c + 1, cb ^ 1);
            CP_COMMIT();
            gen_psi(c + 1, cb ^ 1);
        }

        // ldmatrix base addresses for current buffer
        const uint32_t a_base = sbase + OFF_A + cb * ABUF_BYTES
                              + (warp_m * 64 + (lane & 15)) * ROWB
                              + ((lane >> 4) * 8) * 2;
        const uint32_t b_base = sbase + OFF_B + cb * BBUF_BYTES
                              + (warp_n * 32 + ((lane >> 4) * 8) + (lane & 7)) * ROWB
                              + (((lane >> 3) & 1) * 8) * 2;

        #pragma unroll
        for (int kb = 0; kb < 2; kb++) {       // two k16 blocks per chunk
            uint32_t af[4][4], bf[2][4];
            #pragma unroll
            for (int mb = 0; mb < 4; mb++)
                ldm_x4(af[mb][0], af[mb][1], af[mb][2], af[mb][3],
                       a_base + mb * 16 * ROWB + kb * 32);
            #pragma unroll
            for (int np = 0; np < 2; np++)
                ldm_x4(bf[np][0], bf[np][1], bf[np][2], bf[np][3],
                       b_base + np * 16 * ROWB + kb * 32);
            #pragma unroll
            for (int mb = 0; mb < 4; mb++)
                #pragma unroll
                for (int nb = 0; nb < 4; nb++)
                    mma16816(acc[mb][nb][0], acc[mb][nb][1], acc[mb][nb][2], acc[mb][nb][3],
                             af[mb][0], af[mb][1], af[mb][2], af[mb][3],
                             bf[nb >> 1][(nb & 1) * 2], bf[nb >> 1][(nb & 1) * 2 + 1]);
        }

        if (c + 1 < NCHUNK) CP_WAIT0();
        __syncthreads();
    }

    // ---- epilogue: direct fp32 stores (float2 per fragment row) ----
    {
        const int mw = m0 + warp_m * 64;
        const int nw = n0 + warp_n * 32;
        const int rq = lane >> 2;          // 0..7
        const int cq = 2 * (lane & 3);     // 0,2,4,6
        #pragma unroll
        for (int mb = 0; mb < 4; mb++) {
            #pragma unroll
            for (int nb = 0; nb < 4; nb++) {
                const int row = mw + mb * 16 + rq;
                const int col = nw + nb * 8 + cq;
                *(float2*)(out + (size_t)row * NOUT + col)
                    = make_float2(acc[mb][nb][0], acc[mb][nb][1]);
                *(float2*)(out + (size_t)(row + 8) * NOUT + col)
                    = make_float2(acc[mb][nb][2], acc[mb][nb][3]);
            }
        }
    }
}

extern "C" void kernel_launch(void* const* d_in, const int* in_sizes, int n_in,
                              void* d_out, int out_size) {
    const float* x   = (const float*)d_in[0];
    const float* wgt = (const float*)d_in[1];
    const int*   mi  = (const int*)d_in[2];
    float* out = (float*)d_out;

    convert_w_kernel<<<(NOUT * KPAD) / NTHREADS, NTHREADS>>>(wgt);

    cudaFuncSetAttribute(pce_mma_kernel,
                         cudaFuncAttributeMaxDynamicSharedMemorySize, SMEM_BYTES);
    pce_mma_kernel<<<(NSAMP / MTILE) * (NOUT / NTILE), NTHREADS, SMEM_BYTES>>>(x, mi, out);
}

// round 4
// speedup vs baseline: 1.1873x; 1.1873x over previous
#include <cuda_runtime.h>
#include <cuda_fp16.h>
#include <cstdint>

// ---------------- problem constants ----------------
#define NSAMP   131072
#define INF     8
#define NPCE    495
#define KPAD    512
#define NOUT    256
#define MTILE   128          // CTA rows
#define NTILE   256          // CTA cols (full output width -> psi computed once)
#define KC      32           // K per pipeline chunk
#define NCHUNK  (KPAD / KC)  // 16
#define NTHREADS 512

// A staged k-major: 32 k-rows x 128 m halves, row stride 272B (17 x 16B)
#define AROWB   272
#define ABUF_BYTES (KC * AROWB)          // 8704
// B staged n-major: 256 n-rows x 32 k halves, row stride 80B
#define BROWB   80
#define BBUF_BYTES (NTILE * BROWB)       // 20480

// smem byte layout (dynamic)
#define OFF_MI  0                        // 512*4 = 2048
#define OFF_H   2048                     // 40 rows x 128 floats = 20480 -> 22528
#define OFF_A   22528                    // 2 * 8704  = 17408 -> 39936
#define OFF_B   39936                    // 2 * 20480 = 40960 -> 80896
#define SMEM_BYTES 80896

// fp16 weights, zero-padded K, [NOUT][KPAD]
__device__ __half w16g[NOUT * KPAD];

__global__ void convert_w_kernel(const float* __restrict__ wgt) {
    int idx = blockIdx.x * blockDim.x + threadIdx.x;   // 131072 total
    int n = idx >> 9, k = idx & (KPAD - 1);
    w16g[idx] = __float2half(k < NPCE ? wgt[n * NPCE + k] : 0.0f);
}

static __device__ __forceinline__ uint32_t smem_u32(const void* p) {
    uint32_t a;
    asm("{ .reg .u64 t; cvta.to.shared.u64 t, %1; cvt.u32.u64 %0, t; }" : "=r"(a) : "l"(p));
    return a;
}

static __device__ __forceinline__ void cp_async16(uint32_t dst, const void* src) {
    asm volatile("cp.async.ca.shared.global [%0], [%1], 16;" :: "r"(dst), "l"(src));
}

#define CP_COMMIT() asm volatile("cp.async.commit_group;" ::: "memory")
#define CP_WAIT0()  asm volatile("cp.async.wait_group 0;" ::: "memory")

static __device__ __forceinline__ void ldm_x4(uint32_t& r0, uint32_t& r1,
                                              uint32_t& r2, uint32_t& r3, uint32_t addr) {
    asm volatile("ldmatrix.sync.aligned.m8n8.x4.shared.b16 {%0,%1,%2,%3}, [%4];"
                 : "=r"(r0), "=r"(r1), "=r"(r2), "=r"(r3) : "r"(addr));
}

static __device__ __forceinline__ void ldm_x4_trans(uint32_t& r0, uint32_t& r1,
                                                    uint32_t& r2, uint32_t& r3, uint32_t addr) {
    asm volatile("ldmatrix.sync.aligned.m8n8.x4.trans.shared.b16 {%0,%1,%2,%3}, [%4];"
                 : "=r"(r0), "=r"(r1), "=r"(r2), "=r"(r3) : "r"(addr));
}

static __device__ __forceinline__ void mma16816(float& c0, float& c1, float& c2, float& c3,
                                                uint32_t a0, uint32_t a1, uint32_t a2, uint32_t a3,
                                                uint32_t b0, uint32_t b1) {
    asm volatile(
        "mma.sync.aligned.m16n8k16.row.col.f32.f16.f16.f32 "
        "{%0,%1,%2,%3}, {%4,%5,%6,%7}, {%8,%9}, {%0,%1,%2,%3};"
        : "+f"(c0), "+f"(c1), "+f"(c2), "+f"(c3)
        : "r"(a0), "r"(a1), "r"(a2), "r"(a3), "r"(b0), "r"(b1));
}

extern __shared__ char smem[];

__global__ void __launch_bounds__(NTHREADS, 1)
pce_mma_kernel(const float* __restrict__ x, const int* __restrict__ mi,
               float* __restrict__ out)
{
    const int tid  = threadIdx.x;
    const int wid  = tid >> 5;
    const int lane = tid & 31;
    const int m0   = blockIdx.x * MTILE;

    const uint32_t sbase = smem_u32(smem);
    unsigned* mi_s = (unsigned*)(smem + OFF_MI);
    float*    ht   = (float*)(smem + OFF_H);     // HT[off][m], stride 128 floats

    // ---- pack multi-indices: <= 4 nonzero (dim, order) entries, 8-bit slots.
    //      offset = dim*5 + order in [1, 39]; empty slot -> 0 -> HT[0][m] = 1.
    for (int t = tid; t < KPAD; t += NTHREADS) {
        unsigned packed = 0;
        if (t < NPCE) {
            int slot = 0;
            #pragma unroll
            for (int j = 0; j < INF; j++) {
                int o = mi[t * INF + j];
                if (o > 0) { packed |= (unsigned)(j * 5 + o) << (8 * slot); slot++; }
            }
        }
        mi_s[t] = packed;
    }

    // ---- normalized Hermite table, TRANSPOSED: HT[j][m] (conflict-free build:
    //      per-thread column fixed -> bank = tid%32 distinct across lanes) ----
    if (tid < MTILE) {
        const float4* xr = (const float4*)(x + (size_t)(m0 + tid) * INF);
        float4 xa = xr[0], xb = xr[1];
        float vx[8] = {xa.x, xa.y, xa.z, xa.w, xb.x, xb.y, xb.z, xb.w};
        #pragma unroll
        for (int j = 0; j < INF; j++) {
            float v  = vx[j];
            float h2 = v * v - 1.f;
            float h3 = v * h2 - 2.f * v;
            float h4 = v * h3 - 3.f * h2;
            ht[(j * 5 + 0) * MTILE + tid] = 1.f;
            ht[(j * 5 + 1) * MTILE + tid] = v;
            ht[(j * 5 + 2) * MTILE + tid] = h2 * 0.70710678118654752f;  // 1/sqrt(2!)
            ht[(j * 5 + 3) * MTILE + tid] = h3 * 0.40824829046386302f;  // 1/sqrt(3!)
            ht[(j * 5 + 4) * MTILE + tid] = h4 * 0.20412414523193151f;  // 1/sqrt(4!)
        }
    }
    __syncthreads();

    // ---- pipeline helpers ----
    auto load_B = [&](int c, int buf) {
        // 256 n-rows x 64B = 1024 x 16B chunks, 2 per thread
        const uint32_t bdst = sbase + OFF_B + buf * BBUF_BYTES;
        #pragma unroll
        for (int j = 0; j < 2; j++) {
            int idx = tid + j * NTHREADS;        // 0..1023
            int n = idx >> 2, g = idx & 3;
            cp_async16(bdst + n * BROWB + g * 16,
                       w16g + (size_t)n * KPAD + c * KC + g * 8);
        }
    };

    auto gen_psi = [&](int c, int buf) {
        // A tile k-major [32 k][128 m]; k warp-uniform, m per lane:
        //   mi load = broadcast; HT loads conflict-free; STS contiguous 2B.
        const int k0 = c * KC;
        const uint32_t adst = sbase + OFF_A + buf * ABUF_BYTES;
        #pragma unroll
        for (int i = 0; i < 8; i++) {
            int idx = tid + i * NTHREADS;        // 0..4095
            int k = idx >> 7, m = idx & 127;
            unsigned p = mi_s[k0 + k];
            float v = ht[(p & 255) * MTILE + m] * ht[((p >> 8) & 255) * MTILE + m]
                    * ht[((p >> 16) & 255) * MTILE + m] * ht[(p >> 24) * MTILE + m];
            // k >= NPCE: mi_s = 0 -> v = 1; weight rows zero-padded, harmless
            *(__half*)(smem + OFF_A + buf * ABUF_BYTES + k * AROWB + m * 2)
                = __float2half(v);
            (void)adst;
        }
    };

    // ---- warp tiling: 4(m) x 4(n) warps, each 32m x 64n ----
    const int warp_m = wid >> 2;   // 0..3
    const int warp_n = wid & 3;    // 0..3

    float acc[2][8][4];
    #pragma unroll
    for (int a = 0; a < 2; a++)
        #pragma unroll
        for (int b = 0; b < 8; b++)
            #pragma unroll
            for (int r = 0; r < 4; r++) acc[a][b][r] = 0.f;

    // prologue: fill stage 0
    load_B(0, 0);
    CP_COMMIT();
    gen_psi(0, 0);
    CP_WAIT0();
    __syncthreads();

    // per-warp invariant ldmatrix lane offsets
    const int a_row_off = (lane & 7) + ((lane >> 4) & 1) * 8;   // k within k16 block
    const int a_m_off   = ((lane >> 3) & 1) * 8;                // m sub-block

    for (int c = 0; c < NCHUNK; c++) {
        const int cb = c & 1;
        if (c + 1 < NCHUNK) {
            load_B(c + 1, cb ^ 1);
            CP_COMMIT();
            gen_psi(c + 1, cb ^ 1);
        }

        const uint32_t abase = sbase + OFF_A + cb * ABUF_BYTES;
        const uint32_t b_base = sbase + OFF_B + cb * BBUF_BYTES
                              + (warp_n * 64 + ((lane >> 4) * 8) + (lane & 7)) * BROWB
                              + ((lane >> 3) & 1) * 16;

        #pragma unroll
        for (int kb = 0; kb < 2; kb++) {       // two k16 blocks per chunk
            uint32_t af[2][4], bf[4][4];
            #pragma unroll
            for (int mb = 0; mb < 2; mb++) {
                // A k-major + trans: matrices (k0-7,m0-7),(k0-7,m8-15),(k8-15,m0-7),(k8-15,m8-15)
                uint32_t addr = abase + (kb * 16 + a_row_off) * AROWB
                              + (warp_m * 32 + mb * 16 + a_m_off) * 2;
                ldm_x4_trans(af[mb][0], af[mb][1], af[mb][2], af[mb][3], addr);
            }
            #pragma unroll
            for (int np = 0; np < 4; np++)
                ldm_x4(bf[np][0], bf[np][1], bf[np][2], bf[np][3],
                       b_base + np * 16 * BROWB + kb * 32);
            #pragma unroll
            for (int mb = 0; mb < 2; mb++)
                #pragma unroll
                for (int nb = 0; nb < 8; nb++)
                    mma16816(acc[mb][nb][0], acc[mb][nb][1], acc[mb][nb][2], acc[mb][nb][3],
                             af[mb][0], af[mb][1], af[mb][2], af[mb][3],
                             bf[nb >> 1][(nb & 1) * 2], bf[nb >> 1][(nb & 1) * 2 + 1]);
        }

        if (c + 1 < NCHUNK) CP_WAIT0();
        __syncthreads();
    }

    // ---- epilogue: direct fp32 stores (float2 per fragment row) ----
    {
        const int mw = m0 + warp_m * 32;
        const int nw = warp_n * 64;
        const int rq = lane >> 2;          // 0..7
        const int cq = 2 * (lane & 3);     // 0,2,4,6
        #pragma unroll
        for (int mb = 0; mb < 2; mb++) {
            #pragma unroll
            for (int nb = 0; nb < 8; nb++) {
                const int row = mw + mb * 16 + rq;
                const int col = nw + nb * 8 + cq;
                *(float2*)(out + (size_t)row * NOUT + col)
                    = make_float2(acc[mb][nb][0], acc[mb][nb][1]);
                *(float2*)(out + (size_t)(row + 8) * NOUT + col)
                    = make_float2(acc[mb][nb][2], acc[mb][nb][3]);
            }
        }
    }
}

extern "C" void kernel_launch(void* const* d_in, const int* in_sizes, int n_in,
                              void* d_out, int out_size) {
    const float* x   = (const float*)d_in[0];
    const float* wgt = (const float*)d_in[1];
    const int*   mi  = (const int*)d_in[2];
    float* out = (float*)d_out;

    convert_w_kernel<<<(NOUT * KPAD) / 256, 256>>>(wgt);

    cudaFuncSetAttribute(pce_mma_kernel,
                         cudaFuncAttributeMaxDynamicSharedMemorySize, SMEM_BYTES);
    pce_mma_kernel<<<NSAMP / MTILE, NTHREADS, SMEM_BYTES>>>(x, mi, out);
}